// round 5
// baseline (speedup 1.0000x reference)
#include <cuda_runtime.h>
#include <cuda_bf16.h>

// ---------------------------------------------------------------------------
// GCN forward: h1 = relu(conv(x,W1,b1)); h2 = conv(h1,W2,b2);
// pooled = segment_mean(h2, batch); out = log_softmax(pooled@Wl + bl)
// conv(x,W,b) = dinv ⊙ (Adj_csr · (dinv ⊙ (x@W))) + b   (Adj incl self loops)
// GEMM1 is my 4th launch: ncu's capture slot lands there.
// ---------------------------------------------------------------------------

#define MAXN 100000
#define MAXE 640000
#define MAXCSR (MAXN + MAXE)
#define NGRAPH 64
#define HDIM 128

__device__ __align__(16) float d_bufA[MAXN * HDIM];
__device__ __align__(16) float d_bufB[MAXN * HDIM];
__device__ __align__(16) float d_pool[NGRAPH * HDIM];
__device__ int   d_cnt[MAXN];
__device__ int   d_incl[MAXN];
__device__ int   d_bsum[128];
__device__ int   d_rowptr[MAXN + 1];
__device__ int   d_fill[MAXN];
__device__ int   d_csr[MAXCSR];
__device__ float d_dinv[MAXN];
__device__ int   d_is64;

__device__ __forceinline__ int loadIdx(const void* p, int i) {
    return d_is64 ? (int)((const long long*)p)[i] : ((const int*)p)[i];
}

// ---------------- setup: dtype detect + init cnt/fill + zero pool ----------

__global__ void k_setup(const unsigned int* __restrict__ eiw, int N) {
    int i = blockIdx.x * blockDim.x + threadIdx.x;
    if (i < N) { d_cnt[i] = 1; d_fill[i] = 0; }          // cnt=1: self loop
    if (i < NGRAPH * HDIM) d_pool[i] = 0.f;
    if (blockIdx.x == 0) {
        // int64 (<2^31) => all odd 32-bit words zero; int32 => nonzero sum
        __shared__ unsigned long long ssum;
        if (threadIdx.x == 0) ssum = 0;
        __syncthreads();
        unsigned long long local = 0;
        for (int j = 1 + 2 * threadIdx.x; j < 4096; j += 2 * blockDim.x)
            local += eiw[j];
        atomicAdd(&ssum, local);
        __syncthreads();
        if (threadIdx.x == 0) d_is64 = (ssum == 0ULL) ? 1 : 0;
    }
}

// ---------------- degree count ----------------

__global__ void k_count(const void* __restrict__ ei, int E) {
    int e = blockIdx.x * blockDim.x + threadIdx.x;
    if (e < E) atomicAdd(&d_cnt[loadIdx(ei, E + e)], 1);   // dst row
}

// ---------------- block-level inclusive scan of degrees ----------------

__global__ void k_scan1(int N) {
    __shared__ int s[1024];
    int i = blockIdx.x * 1024 + threadIdx.x;
    int v = (i < N) ? d_cnt[i] : 0;
    if (i < N) d_dinv[i] = rsqrtf((float)v);
    s[threadIdx.x] = v;
    __syncthreads();
    for (int off = 1; off < 1024; off <<= 1) {
        int t = (threadIdx.x >= off) ? s[threadIdx.x - off] : 0;
        __syncthreads();
        s[threadIdx.x] += t;
        __syncthreads();
    }
    if (i < N) d_incl[i] = s[threadIdx.x];
    if (threadIdx.x == 1023) d_bsum[blockIdx.x] = s[1023];
}

// rowptr[i] = incl[i] - cnt[i] + prefix(bsum); rowptr[N] = total
__global__ void k_scan3b(int N, int nb) {
    int i = blockIdx.x * blockDim.x + threadIdx.x;
    if (i == 0) {
        int run = 0;
        for (int b = 0; b < nb; b++) run += d_bsum[b];
        d_rowptr[N] = run;
    }
    if (i < N) {
        int blk = i >> 10, base = 0;
        for (int b = 0; b < blk; b++) base += d_bsum[b];
        d_rowptr[i] = d_incl[i] - d_cnt[i] + base;
    }
}

__global__ void k_csrfill(const void* __restrict__ ei, int E, int N) {
    int id = blockIdx.x * blockDim.x + threadIdx.x;
    if (id >= E + N) return;
    int s, dn;
    if (id < E) { s = loadIdx(ei, id); dn = loadIdx(ei, E + id); }
    else        { s = dn = id - E; }                     // self loop
    int pos = d_rowptr[dn] + atomicAdd(&d_fill[dn], 1);
    d_csr[pos] = s;
}

// ---------------- GEMM: out[row] = dinv[row] * (A[row] @ W), 64-row tiles ----
// srcSel: 0 -> Ain (input x), else d_bufB. Writes d_bufA.

__global__ void __launch_bounds__(256) k_gemm(const float* __restrict__ Ain,
                                              int srcSel,
                                              const float* __restrict__ W,
                                              int N) {
    const float* A = (srcSel == 0) ? Ain : (const float*)d_bufB;
    float* out = d_bufA;

    __shared__ __align__(16) float As[128][68];   // transposed: As[k][r]
    int tid  = threadIdx.x;
    int row0 = blockIdx.x * 64;

    for (int idx = tid; idx < 64 * 128; idx += 256) {
        int r = idx >> 7, k = idx & 127;
        int row = row0 + r;
        As[k][r] = (row < N) ? A[(long long)row * 128 + k] : 0.f;
    }
    __syncthreads();

    int tx = tid & 15, ty = tid >> 4;      // cols tx*8..+7, rows ty*4..+3
    float acc[4][8];
#pragma unroll
    for (int i = 0; i < 4; i++)
#pragma unroll
        for (int j = 0; j < 8; j++) acc[i][j] = 0.f;

    const float* Wp = W + tx * 8;
#pragma unroll 8
    for (int k = 0; k < 128; k++) {
        float4 a  = *(const float4*)&As[k][ty * 4];
        float4 w0 = __ldg((const float4*)(Wp + k * 128));
        float4 w1 = __ldg((const float4*)(Wp + k * 128 + 4));
        float av[4] = {a.x, a.y, a.z, a.w};
        float wv[8] = {w0.x, w0.y, w0.z, w0.w, w1.x, w1.y, w1.z, w1.w};
#pragma unroll
        for (int i = 0; i < 4; i++)
#pragma unroll
            for (int j = 0; j < 8; j++) acc[i][j] += av[i] * wv[j];
    }

#pragma unroll
    for (int i = 0; i < 4; i++) {
        int row = row0 + ty * 4 + i;
        if (row < N) {
            float dd = d_dinv[row];
            float4 o0 = make_float4(acc[i][0]*dd, acc[i][1]*dd, acc[i][2]*dd, acc[i][3]*dd);
            float4 o1 = make_float4(acc[i][4]*dd, acc[i][5]*dd, acc[i][6]*dd, acc[i][7]*dd);
            *(float4*)&out[(long long)row * 128 + tx * 8]     = o0;
            *(float4*)&out[(long long)row * 128 + tx * 8 + 4] = o1;
        }
    }
}

// ---------------- Aggregation: warp per node ----------------

template <bool RELU>
__global__ void k_agg(const float* __restrict__ bias, int N) {
    int w    = (blockIdx.x * blockDim.x + threadIdx.x) >> 5;
    int lane = threadIdx.x & 31;
    if (w >= N) return;
    int rs = d_rowptr[w], re = d_rowptr[w + 1];
    const float4* in4 = (const float4*)d_bufA;
    float4 acc = make_float4(0.f, 0.f, 0.f, 0.f);
    for (int e = rs; e < re; e++) {
        int s = d_csr[e];
        float4 v = __ldg(&in4[s * 32 + lane]);
        acc.x += v.x; acc.y += v.y; acc.z += v.z; acc.w += v.w;
    }
    float dd = d_dinv[w];
    float4 b = __ldg(&((const float4*)bias)[lane]);
    float4 o = make_float4(acc.x * dd + b.x, acc.y * dd + b.y,
                           acc.z * dd + b.z, acc.w * dd + b.w);
    if (RELU) {
        o.x = fmaxf(o.x, 0.f); o.y = fmaxf(o.y, 0.f);
        o.z = fmaxf(o.z, 0.f); o.w = fmaxf(o.w, 0.f);
    }
    ((float4*)d_bufB)[w * 32 + lane] = o;
}

// ---------------- Pool: chunked partial sums + atomics (batch sorted) ------

__global__ void k_poolacc(const void* __restrict__ batch, int N) {
    int c = threadIdx.x;                 // 0..127
    int start = blockIdx.x * 1024;
    if (start >= N) return;
    int end = min(start + 1024, N);
    int curg = loadIdx(batch, start);
    float run = 0.f;
    for (int i = start; i < end; i++) {
        int g = loadIdx(batch, i);
        if (g != curg) {
            atomicAdd(&d_pool[curg * 128 + c], run);
            run = 0.f; curg = g;
        }
        run += d_bufB[(long long)i * 128 + c];
    }
    atomicAdd(&d_pool[curg * 128 + c], run);
}

// ---------------- Final: counts + logits + log_softmax ----------------

__global__ void k_final(const float* __restrict__ Wl, const float* __restrict__ bl,
                        const void* __restrict__ batch, int N,
                        float* __restrict__ out) {
    __shared__ float sl[NGRAPH][10];
    __shared__ float sm[NGRAPH];
    __shared__ float ss[NGRAPH];
    __shared__ float scnt[NGRAPH + 1];
    int tid = threadIdx.x;               // 640 threads
    if (tid <= NGRAPH) {
        int lo = 0, hi = N;
        while (lo < hi) { int mid = (lo + hi) >> 1; if (loadIdx(batch, mid) < tid) lo = mid + 1; else hi = mid; }
        scnt[tid] = (float)lo;
    }
    __syncthreads();
    int g = tid / 10, c = tid % 10;
    if (tid < NGRAPH * 10) {
        float cnt = fmaxf(scnt[g + 1] - scnt[g], 1.0f);
        float dot = 0.f;
        for (int k = 0; k < 128; k++) dot += d_pool[g * 128 + k] * Wl[k * 10 + c];
        sl[g][c] = dot / cnt + bl[c];
    }
    __syncthreads();
    if (tid < NGRAPH) {
        float m = -1e30f;
        for (int j = 0; j < 10; j++) m = fmaxf(m, sl[tid][j]);
        float s = 0.f;
        for (int j = 0; j < 10; j++) s += expf(sl[tid][j] - m);
        sm[tid] = m; ss[tid] = logf(s);
    }
    __syncthreads();
    if (tid < NGRAPH * 10) out[tid] = sl[g][c] - sm[g] - ss[g];
}

// ---------------- Launch ----------------

extern "C" void kernel_launch(void* const* d_in, const int* in_sizes, int n_in,
                              void* d_out, int out_size) {
    (void)n_in; (void)out_size;
    const float* x     = (const float*)d_in[0];
    const void*  ei    = d_in[1];
    const void*  batch = d_in[2];
    const float* W1    = (const float*)d_in[3];
    const float* b1    = (const float*)d_in[4];
    const float* W2    = (const float*)d_in[5];
    const float* b2    = (const float*)d_in[6];
    const float* Wl    = (const float*)d_in[7];
    const float* bl    = (const float*)d_in[8];
    float* out = (float*)d_out;

    int N = in_sizes[0] / HDIM;
    int E = in_sizes[1] / 2;
    int nb = (N + 1023) >> 10;

    // ncu capture slot = my 4th launch -> put GEMM1 there.
    // GEMM1 only needs d_dinv (from k_scan1); CSR build continues after it.
    k_setup <<<(N + 255) / 256, 256>>>((const unsigned int*)ei, N);        // 1
    k_count <<<(E + 255) / 256, 256>>>(ei, E);                             // 2
    k_scan1 <<<nb, 1024>>>(N);                                             // 3
    k_gemm  <<<(N + 63) / 64, 256>>>(x, 0, W1, N);                         // 4 <- profiled
    k_scan3b<<<(N + 255) / 256, 256>>>(N, nb);                             // 5
    k_csrfill<<<(E + N + 255) / 256, 256>>>(ei, E, N);                     // 6
    k_agg<true><<<((long long)N * 32 + 255) / 256, 256>>>(b1, N);          // 7

    // conv2
    k_gemm<<<(N + 63) / 64, 256>>>(nullptr, 2, W2, N);                     // 8
    k_agg<false><<<((long long)N * 32 + 255) / 256, 256>>>(b2, N);         // 9

    // pool + classifier
    k_poolacc<<<(N + 1023) / 1024, 128>>>(batch, N);                       // 10
    k_final<<<1, 640>>>(Wl, bl, batch, N, out);                            // 11
}

// round 6
// speedup vs baseline: 1.9413x; 1.9413x over previous
#include <cuda_runtime.h>
#include <cuda_bf16.h>

// ---------------------------------------------------------------------------
// GCN forward: h1 = relu(conv(x,W1,b1)); h2 = conv(h1,W2,b2);
// pooled = segment_mean(h2, batch); out = log_softmax(pooled@Wl + bl)
// conv(x,W,b) = dinv ⊙ (Adj_csr · (dinv ⊙ (x@W))) + b   (Adj incl self loops)
// GEMM1 is my 4th launch (ncu capture slot).
// ---------------------------------------------------------------------------

#define MAXN 100000
#define MAXE 640000
#define MAXCSR (MAXN + MAXE)
#define NGRAPH 64
#define HDIM 128

__device__ __align__(16) float d_bufA[MAXN * HDIM];
__device__ __align__(16) float d_bufB[MAXN * HDIM];
__device__ __align__(16) float d_pool[NGRAPH * HDIM];
__device__ int   d_cnt[MAXN];
__device__ int   d_incl[MAXN];
__device__ int   d_bsum[128];
__device__ int   d_rowptr[MAXN + 1];
__device__ int   d_fill[MAXN];
__device__ int   d_csr[MAXCSR];
__device__ float d_dinv[MAXN];
__device__ int   d_is64;

__device__ __forceinline__ int loadIdx(const void* p, int i) {
    return d_is64 ? (int)((const long long*)p)[i] : ((const int*)p)[i];
}

// ---------------- setup: dtype detect + init cnt/fill ----------------------

__global__ void k_setup(const unsigned int* __restrict__ eiw, int N) {
    int i = blockIdx.x * blockDim.x + threadIdx.x;
    if (i < N) { d_cnt[i] = 1; d_fill[i] = 0; }          // cnt=1: self loop
    if (blockIdx.x == 0) {
        // int64 (<2^31) => all odd 32-bit words zero; int32 => nonzero sum
        __shared__ unsigned long long ssum;
        if (threadIdx.x == 0) ssum = 0;
        __syncthreads();
        unsigned long long local = 0;
        for (int j = 1 + 2 * threadIdx.x; j < 4096; j += 2 * blockDim.x)
            local += eiw[j];
        atomicAdd(&ssum, local);
        __syncthreads();
        if (threadIdx.x == 0) d_is64 = (ssum == 0ULL) ? 1 : 0;
    }
}

// ---------------- degree count ----------------

__global__ void k_count(const void* __restrict__ ei, int E) {
    int e = blockIdx.x * blockDim.x + threadIdx.x;
    if (e < E) atomicAdd(&d_cnt[loadIdx(ei, E + e)], 1);   // dst row
}

// ---------------- block-level inclusive scan of degrees ----------------

__global__ void k_scan1(int N) {
    __shared__ int s[1024];
    int i = blockIdx.x * 1024 + threadIdx.x;
    int v = (i < N) ? d_cnt[i] : 0;
    if (i < N) d_dinv[i] = rsqrtf((float)v);
    s[threadIdx.x] = v;
    __syncthreads();
    for (int off = 1; off < 1024; off <<= 1) {
        int t = (threadIdx.x >= off) ? s[threadIdx.x - off] : 0;
        __syncthreads();
        s[threadIdx.x] += t;
        __syncthreads();
    }
    if (i < N) d_incl[i] = s[threadIdx.x];
    if (threadIdx.x == 1023) d_bsum[blockIdx.x] = s[1023];
}

// rowptr[i] = incl[i] - cnt[i] + prefix(bsum); rowptr[N] = total
__global__ void k_scan3b(int N, int nb) {
    int i = blockIdx.x * blockDim.x + threadIdx.x;
    if (i == 0) {
        int run = 0;
        for (int b = 0; b < nb; b++) run += d_bsum[b];
        d_rowptr[N] = run;
    }
    if (i < N) {
        int blk = i >> 10, base = 0;
        for (int b = 0; b < blk; b++) base += d_bsum[b];
        d_rowptr[i] = d_incl[i] - d_cnt[i] + base;
    }
}

__global__ void k_csrfill(const void* __restrict__ ei, int E, int N) {
    int id = blockIdx.x * blockDim.x + threadIdx.x;
    if (id >= E + N) return;
    int s, dn;
    if (id < E) { s = loadIdx(ei, id); dn = loadIdx(ei, E + id); }
    else        { s = dn = id - E; }                     // self loop
    int pos = d_rowptr[dn] + atomicAdd(&d_fill[dn], 1);
    d_csr[pos] = s;
}

// ---------------- GEMM: out = dinv ⊙ (A @ W), 64-row tile, 8x8/thread ------
// 128 threads: tx in [0,16) -> 8 cols, ty in [0,8) -> 8 rows.
// Halves W L1 traffic per FLOP vs the 4x8 variant (L1 was the binding pipe).

__global__ void __launch_bounds__(128) k_gemm(const float* __restrict__ Ain,
                                              int srcSel,
                                              const float* __restrict__ W,
                                              int N) {
    const float* A = (srcSel == 0) ? Ain : (const float*)d_bufB;
    float* out = d_bufA;

    __shared__ __align__(16) float As[128][68];   // transposed: As[k][r]
    int tid  = threadIdx.x;
    int row0 = blockIdx.x * 64;

    for (int idx = tid; idx < 64 * 128; idx += 128) {
        int r = idx >> 7, k = idx & 127;
        int row = row0 + r;
        As[k][r] = (row < N) ? A[(long long)row * 128 + k] : 0.f;
    }
    __syncthreads();

    int tx = tid & 15, ty = tid >> 4;      // cols tx*8..+7, rows ty*8..+7
    float acc[8][8];
#pragma unroll
    for (int i = 0; i < 8; i++)
#pragma unroll
        for (int j = 0; j < 8; j++) acc[i][j] = 0.f;

    const float* Wp = W + tx * 8;
#pragma unroll 4
    for (int k = 0; k < 128; k++) {
        float4 a0 = *(const float4*)&As[k][ty * 8];
        float4 a1 = *(const float4*)&As[k][ty * 8 + 4];
        float4 w0 = __ldg((const float4*)(Wp + k * 128));
        float4 w1 = __ldg((const float4*)(Wp + k * 128 + 4));
        float av[8] = {a0.x, a0.y, a0.z, a0.w, a1.x, a1.y, a1.z, a1.w};
        float wv[8] = {w0.x, w0.y, w0.z, w0.w, w1.x, w1.y, w1.z, w1.w};
#pragma unroll
        for (int i = 0; i < 8; i++)
#pragma unroll
            for (int j = 0; j < 8; j++) acc[i][j] += av[i] * wv[j];
    }

#pragma unroll
    for (int i = 0; i < 8; i++) {
        int row = row0 + ty * 8 + i;
        if (row < N) {
            float dd = d_dinv[row];
            float4 o0 = make_float4(acc[i][0]*dd, acc[i][1]*dd, acc[i][2]*dd, acc[i][3]*dd);
            float4 o1 = make_float4(acc[i][4]*dd, acc[i][5]*dd, acc[i][6]*dd, acc[i][7]*dd);
            *(float4*)&out[(long long)row * 128 + tx * 8]     = o0;
            *(float4*)&out[(long long)row * 128 + tx * 8 + 4] = o1;
        }
    }
}

// ---------------- Aggregation: warp per node ----------------

template <bool RELU>
__global__ void k_agg(const float* __restrict__ bias, int N) {
    int w    = (blockIdx.x * blockDim.x + threadIdx.x) >> 5;
    int lane = threadIdx.x & 31;
    if (w >= N) return;
    int rs = d_rowptr[w], re = d_rowptr[w + 1];
    const float4* in4 = (const float4*)d_bufA;
    float4 acc = make_float4(0.f, 0.f, 0.f, 0.f);
    for (int e = rs; e < re; e++) {
        int s = d_csr[e];
        float4 v = __ldg(&in4[s * 32 + lane]);
        acc.x += v.x; acc.y += v.y; acc.z += v.z; acc.w += v.w;
    }
    float dd = d_dinv[w];
    float4 b = __ldg(&((const float4*)bias)[lane]);
    float4 o = make_float4(acc.x * dd + b.x, acc.y * dd + b.y,
                           acc.z * dd + b.z, acc.w * dd + b.w);
    if (RELU) {
        o.x = fmaxf(o.x, 0.f); o.y = fmaxf(o.y, 0.f);
        o.z = fmaxf(o.z, 0.f); o.w = fmaxf(o.w, 0.f);
    }
    ((float4*)d_bufB)[w * 32 + lane] = o;
}

// ---------------- Mean pool per graph (batch sorted, branch-free loop) -----

__global__ void k_pool(const void* __restrict__ batch, int N) {
    int g = blockIdx.x;        // 0..63
    int c = threadIdx.x;       // 0..127
    int lo = 0, hi = N;
    while (lo < hi) { int mid = (lo + hi) >> 1; if (loadIdx(batch, mid) < g) lo = mid + 1; else hi = mid; }
    int s = lo;
    lo = s; hi = N;
    while (lo < hi) { int mid = (lo + hi) >> 1; if (loadIdx(batch, mid) < g + 1) lo = mid + 1; else hi = mid; }
    int e = lo;
    float sum = 0.f;
    for (int i = s; i < e; i++) sum += d_bufB[(long long)i * 128 + c];
    float cnt = (float)((e - s) > 0 ? (e - s) : 1);
    d_pool[g * 128 + c] = sum / cnt;
}

// ---------------- Final: logits + log_softmax ----------------

__global__ void k_final(const float* __restrict__ Wl, const float* __restrict__ bl,
                        float* __restrict__ out) {
    __shared__ float sl[NGRAPH][10];
    __shared__ float sm[NGRAPH];
    __shared__ float ss[NGRAPH];
    int tid = threadIdx.x;                // 640 threads
    int g = tid / 10, c = tid % 10;
    if (tid < NGRAPH * 10) {
        float dot = bl[c];
        for (int k = 0; k < 128; k++) dot += d_pool[g * 128 + k] * Wl[k * 10 + c];
        sl[g][c] = dot;
    }
    __syncthreads();
    if (tid < NGRAPH) {
        float m = -1e30f;
        for (int j = 0; j < 10; j++) m = fmaxf(m, sl[tid][j]);
        float s = 0.f;
        for (int j = 0; j < 10; j++) s += expf(sl[tid][j] - m);
        sm[tid] = m; ss[tid] = logf(s);
    }
    __syncthreads();
    if (tid < NGRAPH * 10) out[tid] = sl[g][c] - sm[g] - ss[g];
}

// ---------------- Launch ----------------

extern "C" void kernel_launch(void* const* d_in, const int* in_sizes, int n_in,
                              void* d_out, int out_size) {
    (void)n_in; (void)out_size;
    const float* x     = (const float*)d_in[0];
    const void*  ei    = d_in[1];
    const void*  batch = d_in[2];
    const float* W1    = (const float*)d_in[3];
    const float* b1    = (const float*)d_in[4];
    const float* W2    = (const float*)d_in[5];
    const float* b2    = (const float*)d_in[6];
    const float* Wl    = (const float*)d_in[7];
    const float* bl    = (const float*)d_in[8];
    float* out = (float*)d_out;

    int N = in_sizes[0] / HDIM;
    int E = in_sizes[1] / 2;
    int nb = (N + 1023) >> 10;

    // ncu capture slot = my 4th launch -> GEMM1 there.
    k_setup <<<(N + 255) / 256, 256>>>((const unsigned int*)ei, N);        // 1
    k_count <<<(E + 255) / 256, 256>>>(ei, E);                             // 2
    k_scan1 <<<nb, 1024>>>(N);                                             // 3
    k_gemm  <<<(N + 63) / 64, 128>>>(x, 0, W1, N);                         // 4 <- profiled
    k_scan3b<<<(N + 255) / 256, 256>>>(N, nb);                             // 5
    k_csrfill<<<(E + N + 255) / 256, 256>>>(ei, E, N);                     // 6
    k_agg<true><<<((long long)N * 32 + 255) / 256, 256>>>(b1, N);          // 7

    // conv2
    k_gemm<<<(N + 63) / 64, 128>>>(nullptr, 2, W2, N);                     // 8
    k_agg<false><<<((long long)N * 32 + 255) / 256, 256>>>(b2, N);         // 9

    // pool + classifier
    k_pool<<<NGRAPH, HDIM>>>(batch, N);                                    // 10
    k_final<<<1, 640>>>(Wl, bl, out);                                      // 11
}

// round 8
// speedup vs baseline: 2.7730x; 1.4284x over previous
#include <cuda_runtime.h>
#include <cuda_bf16.h>
#include <cstdint>

// ---------------------------------------------------------------------------
// GCN forward with mma.sync (bf16 HMMA) GEMMs — sm_100 baseline ISA only.
// h1 = relu(conv(x,W1,b1)); h2 = conv(h1,W2,b2); pooled = segment_mean(h2);
// out = log_softmax(pooled@Wl + bl)
// conv(x,W,b) = dinv ⊙ (Adj_csr · (dinv ⊙ (x@W))) + b
// GEMM1 is my 4th launch (ncu capture slot).
// ---------------------------------------------------------------------------

#define MAXN 100000
#define MAXE 640000
#define MAXCSR (MAXN + MAXE)
#define NGRAPH 64
#define HDIM 128

__device__ __align__(16) float d_bufA[MAXN * HDIM];
__device__ __align__(16) float d_bufB[MAXN * HDIM];
__device__ __align__(16) float d_pool[NGRAPH * HDIM];
__device__ __align__(16) __nv_bfloat16 d_Wbf1[HDIM * HDIM];  // bf16 copy of W1 [K][N]
__device__ __align__(16) __nv_bfloat16 d_Wbf2[HDIM * HDIM];  // bf16 copy of W2 [K][N]
__device__ int   d_cnt[MAXN];
__device__ int   d_incl[MAXN];
__device__ int   d_bsum[128];
__device__ int   d_rowptr[MAXN + 1];
__device__ int   d_fill[MAXN];
__device__ int   d_csr[MAXCSR];
__device__ float d_dinv[MAXN];
__device__ int   d_is64;

__device__ __forceinline__ int loadIdx(const void* p, int i) {
    return d_is64 ? (int)((const long long*)p)[i] : ((const int*)p)[i];
}

__device__ __forceinline__ uint32_t smem_u32(const void* p) {
    uint32_t a;
    asm("{ .reg .u64 t; cvta.to.shared.u64 t, %1; cvt.u32.u64 %0, t; }" : "=r"(a) : "l"(p));
    return a;
}

// ---------------- setup: dtype detect + init cnt/fill ----------------------

__global__ void k_setup(const unsigned int* __restrict__ eiw, int N) {
    int i = blockIdx.x * blockDim.x + threadIdx.x;
    if (i < N) { d_cnt[i] = 1; d_fill[i] = 0; }          // cnt=1: self loop
    if (blockIdx.x == 0) {
        __shared__ unsigned long long ssum;
        if (threadIdx.x == 0) ssum = 0;
        __syncthreads();
        unsigned long long local = 0;
        for (int j = 1 + 2 * threadIdx.x; j < 4096; j += 2 * blockDim.x)
            local += eiw[j];
        atomicAdd(&ssum, local);
        __syncthreads();
        if (threadIdx.x == 0) d_is64 = (ssum == 0ULL) ? 1 : 0;
    }
}

// ---------------- degree count (+ W -> bf16 images, same [K][N] layout) ----

__global__ void k_count(const void* __restrict__ ei, int E,
                        const float* __restrict__ W1, const float* __restrict__ W2) {
    int e = blockIdx.x * blockDim.x + threadIdx.x;
    if (e < E) atomicAdd(&d_cnt[loadIdx(ei, E + e)], 1);   // dst row
    if (blockIdx.x < 64) {
        int idx = blockIdx.x * 256 + threadIdx.x;          // 0..16383
        d_Wbf1[idx] = __float2bfloat16(W1[idx]);
        d_Wbf2[idx] = __float2bfloat16(W2[idx]);
    }
}

// ---------------- block-level inclusive scan of degrees ----------------

__global__ void k_scan1(int N) {
    __shared__ int s[1024];
    int i = blockIdx.x * 1024 + threadIdx.x;
    int v = (i < N) ? d_cnt[i] : 0;
    if (i < N) d_dinv[i] = rsqrtf((float)v);
    s[threadIdx.x] = v;
    __syncthreads();
    for (int off = 1; off < 1024; off <<= 1) {
        int t = (threadIdx.x >= off) ? s[threadIdx.x - off] : 0;
        __syncthreads();
        s[threadIdx.x] += t;
        __syncthreads();
    }
    if (i < N) d_incl[i] = s[threadIdx.x];
    if (threadIdx.x == 1023) d_bsum[blockIdx.x] = s[1023];
}

__global__ void k_scan3b(int N, int nb) {
    int i = blockIdx.x * blockDim.x + threadIdx.x;
    if (i == 0) {
        int run = 0;
        for (int b = 0; b < nb; b++) run += d_bsum[b];
        d_rowptr[N] = run;
    }
    if (i < N) {
        int blk = i >> 10, base = 0;
        for (int b = 0; b < blk; b++) base += d_bsum[b];
        d_rowptr[i] = d_incl[i] - d_cnt[i] + base;
    }
}

__global__ void k_csrfill(const void* __restrict__ ei, int E, int N) {
    int id = blockIdx.x * blockDim.x + threadIdx.x;
    if (id >= E + N) return;
    int s, dn;
    if (id < E) { s = loadIdx(ei, id); dn = loadIdx(ei, E + id); }
    else        { s = dn = id - E; }                     // self loop
    int pos = d_rowptr[dn] + atomicAdd(&d_fill[dn], 1);
    d_csr[pos] = s;
}

// ---------------- HMMA GEMM: out = dinv ⊙ (A @ W), 128x128 tile ------------
// 256 threads = 8 warps; warp tile 32x64 (2 x m16, 8 x n8), K in 8 steps of 16.
// A fp32 -> bf16 into smem (stride 136 for conflict-free ldmatrix); W bf16 smem.

#define SSTRIDE 136

__global__ void __launch_bounds__(256) k_gemmT(const float* __restrict__ Ain,
                                               int srcSel, int N) {
    const float* A = (srcSel == 0) ? Ain : (const float*)d_bufB;
    const __nv_bfloat16* Wg = (srcSel == 0) ? d_Wbf1 : d_Wbf2;
    float* out = d_bufA;

    extern __shared__ __align__(16) __nv_bfloat16 sm[];
    __nv_bfloat16* sA = sm;                    // [128][SSTRIDE]
    __nv_bfloat16* sB = sm + 128 * SSTRIDE;    // [128][SSTRIDE]

    int tid = threadIdx.x;
    int row0 = blockIdx.x * 128;

    // A tile: fp32 -> bf16 (coalesced float4 = 4 cols), 4096 float4s
    for (int i = tid; i < 4096; i += 256) {
        int r = i >> 5, c4 = i & 31;
        float4 v = (row0 + r < N)
            ? ((const float4*)A)[(long long)(row0 + r) * 32 + c4]
            : make_float4(0.f, 0.f, 0.f, 0.f);
        __nv_bfloat162 p0 = __floats2bfloat162_rn(v.x, v.y);
        __nv_bfloat162 p1 = __floats2bfloat162_rn(v.z, v.w);
        *(__nv_bfloat162*)&sA[r * SSTRIDE + c4 * 4]     = p0;
        *(__nv_bfloat162*)&sA[r * SSTRIDE + c4 * 4 + 2] = p1;
    }
    // B tile: bf16 [128][128] -> smem stride 136, 16B chunks
    for (int i = tid; i < 2048; i += 256) {
        int r = i >> 4, c8 = i & 15;
        uint4 v = ((const uint4*)Wg)[i];
        *(uint4*)&sB[r * SSTRIDE + c8 * 8] = v;
    }
    __syncthreads();

    int warp = tid >> 5, lane = tid & 31;
    int wm = warp >> 1, wn = warp & 1;         // 4x2 warp grid
    int m_base = wm * 32, n_base = wn * 64;

    float acc[2][8][4];
#pragma unroll
    for (int mt = 0; mt < 2; mt++)
#pragma unroll
        for (int nt = 0; nt < 8; nt++)
#pragma unroll
            for (int q = 0; q < 4; q++) acc[mt][nt][q] = 0.f;

    uint32_t sAu = smem_u32(sA), sBu = smem_u32(sB);
    int lrow = lane & 15, lhalf = lane >> 4;   // ldmatrix address split

#pragma unroll
    for (int k0 = 0; k0 < 128; k0 += 16) {
        uint32_t a[2][4];
#pragma unroll
        for (int mt = 0; mt < 2; mt++) {
            uint32_t addr = sAu + (uint32_t)(((m_base + mt * 16 + lrow) * SSTRIDE
                                              + k0 + lhalf * 8) * 2);
            asm volatile("ldmatrix.sync.aligned.m8n8.x4.shared.b16 {%0,%1,%2,%3}, [%4];"
                         : "=r"(a[mt][0]), "=r"(a[mt][1]), "=r"(a[mt][2]), "=r"(a[mt][3])
                         : "r"(addr));
        }
        uint32_t b[4][4];
#pragma unroll
        for (int ng = 0; ng < 4; ng++) {
            uint32_t addr = sBu + (uint32_t)(((k0 + lrow) * SSTRIDE
                                              + n_base + ng * 16 + lhalf * 8) * 2);
            asm volatile("ldmatrix.sync.aligned.m8n8.x4.trans.shared.b16 {%0,%1,%2,%3}, [%4];"
                         : "=r"(b[ng][0]), "=r"(b[ng][1]), "=r"(b[ng][2]), "=r"(b[ng][3])
                         : "r"(addr));
        }
#pragma unroll
        for (int mt = 0; mt < 2; mt++)
#pragma unroll
            for (int nt = 0; nt < 8; nt++) {
                uint32_t b0 = b[nt >> 1][(nt & 1) * 2];
                uint32_t b1 = b[nt >> 1][(nt & 1) * 2 + 1];
                asm volatile(
                    "mma.sync.aligned.m16n8k16.row.col.f32.bf16.bf16.f32 "
                    "{%0,%1,%2,%3}, {%4,%5,%6,%7}, {%8,%9}, {%0,%1,%2,%3};"
                    : "+f"(acc[mt][nt][0]), "+f"(acc[mt][nt][1]),
                      "+f"(acc[mt][nt][2]), "+f"(acc[mt][nt][3])
                    : "r"(a[mt][0]), "r"(a[mt][1]), "r"(a[mt][2]), "r"(a[mt][3]),
                      "r"(b0), "r"(b1));
            }
    }

    // epilogue: frag (c0,c1)@row=lane>>2, (c2,c3)@row+8; cols (lane&3)*2 (+1)
    int rhi = lane >> 2, clo = (lane & 3) * 2;
#pragma unroll
    for (int mt = 0; mt < 2; mt++) {
        int rA = row0 + m_base + mt * 16 + rhi;
        int rB = rA + 8;
        float ddA = (rA < N) ? d_dinv[rA] : 0.f;
        float ddB = (rB < N) ? d_dinv[rB] : 0.f;
#pragma unroll
        for (int nt = 0; nt < 8; nt++) {
            int col = n_base + nt * 8 + clo;
            if (rA < N) {
                float2 v = make_float2(acc[mt][nt][0] * ddA, acc[mt][nt][1] * ddA);
                *(float2*)&out[(long long)rA * 128 + col] = v;
            }
            if (rB < N) {
                float2 v = make_float2(acc[mt][nt][2] * ddB, acc[mt][nt][3] * ddB);
                *(float2*)&out[(long long)rB * 128 + col] = v;
            }
        }
    }
}

// ---------------- Aggregation: warp per node ----------------

template <bool RELU>
__global__ void k_agg(const float* __restrict__ bias, int N) {
    int w    = (blockIdx.x * blockDim.x + threadIdx.x) >> 5;
    int lane = threadIdx.x & 31;
    if (w >= N) return;
    int rs = d_rowptr[w], re = d_rowptr[w + 1];
    const float4* in4 = (const float4*)d_bufA;
    float4 acc = make_float4(0.f, 0.f, 0.f, 0.f);
    for (int e = rs; e < re; e++) {
        int s = d_csr[e];
        float4 v = __ldg(&in4[s * 32 + lane]);
        acc.x += v.x; acc.y += v.y; acc.z += v.z; acc.w += v.w;
    }
    float dd = d_dinv[w];
    float4 b = __ldg(&((const float4*)bias)[lane]);
    float4 o = make_float4(acc.x * dd + b.x, acc.y * dd + b.y,
                           acc.z * dd + b.z, acc.w * dd + b.w);
    if (RELU) {
        o.x = fmaxf(o.x, 0.f); o.y = fmaxf(o.y, 0.f);
        o.z = fmaxf(o.z, 0.f); o.w = fmaxf(o.w, 0.f);
    }
    ((float4*)d_bufB)[w * 32 + lane] = o;
}

// ---------------- Mean pool per graph (batch sorted, branch-free) ----------

__global__ void k_pool(const void* __restrict__ batch, int N) {
    int g = blockIdx.x;        // 0..63
    int c = threadIdx.x;       // 0..127
    int lo = 0, hi = N;
    while (lo < hi) { int mid = (lo + hi) >> 1; if (loadIdx(batch, mid) < g) lo = mid + 1; else hi = mid; }
    int s = lo;
    lo = s; hi = N;
    while (lo < hi) { int mid = (lo + hi) >> 1; if (loadIdx(batch, mid) < g + 1) lo = mid + 1; else hi = mid; }
    int e = lo;
    float sum = 0.f;
    for (int i = s; i < e; i++) sum += d_bufB[(long long)i * 128 + c];
    float cnt = (float)((e - s) > 0 ? (e - s) : 1);
    d_pool[g * 128 + c] = sum / cnt;
}

// ---------------- Final: logits + log_softmax ----------------

__global__ void k_final(const float* __restrict__ Wl, const float* __restrict__ bl,
                        float* __restrict__ out) {
    __shared__ float sl[NGRAPH][10];
    __shared__ float sm[NGRAPH];
    __shared__ float ss[NGRAPH];
    int tid = threadIdx.x;                // 640 threads
    int g = tid / 10, c = tid % 10;
    if (tid < NGRAPH * 10) {
        float dot = bl[c];
        for (int k = 0; k < 128; k++) dot += d_pool[g * 128 + k] * Wl[k * 10 + c];
        sl[g][c] = dot;
    }
    __syncthreads();
    if (tid < NGRAPH) {
        float m = -1e30f;
        for (int j = 0; j < 10; j++) m = fmaxf(m, sl[tid][j]);
        float s = 0.f;
        for (int j = 0; j < 10; j++) s += expf(sl[tid][j] - m);
        sm[tid] = m; ss[tid] = logf(s);
    }
    __syncthreads();
    if (tid < NGRAPH * 10) out[tid] = sl[g][c] - sm[g] - ss[g];
}

// ---------------- Launch ----------------

extern "C" void kernel_launch(void* const* d_in, const int* in_sizes, int n_in,
                              void* d_out, int out_size) {
    (void)n_in; (void)out_size;
    const float* x     = (const float*)d_in[0];
    const void*  ei    = d_in[1];
    const void*  batch = d_in[2];
    const float* W1    = (const float*)d_in[3];
    const float* b1    = (const float*)d_in[4];
    const float* W2    = (const float*)d_in[5];
    const float* b2    = (const float*)d_in[6];
    const float* Wl    = (const float*)d_in[7];
    const float* bl    = (const float*)d_in[8];
    float* out = (float*)d_out;

    int N = in_sizes[0] / HDIM;
    int E = in_sizes[1] / 2;
    int nb = (N + 1023) >> 10;

    const int GSMEM = 2 * 128 * SSTRIDE * 2;   // 69632 bytes
    static int smemSet = 0;
    if (!smemSet) {
        cudaFuncSetAttribute(k_gemmT, cudaFuncAttributeMaxDynamicSharedMemorySize, GSMEM);
        smemSet = 1;
    }

    // ncu capture slot = my 4th launch -> GEMM1 there.
    k_setup <<<(N + 255) / 256, 256>>>((const unsigned int*)ei, N);        // 1
    k_count <<<(E + 255) / 256, 256>>>(ei, E, W1, W2);                     // 2 (+W bf16)
    k_scan1 <<<nb, 1024>>>(N);                                             // 3
    k_gemmT <<<(N + 127) / 128, 256, GSMEM>>>(x, 0, N);                    // 4 <- profiled
    k_scan3b<<<(N + 255) / 256, 256>>>(N, nb);                             // 5
    k_csrfill<<<(E + N + 255) / 256, 256>>>(ei, E, N);                     // 6
    k_agg<true><<<((long long)N * 32 + 255) / 256, 256>>>(b1, N);          // 7

    // conv2
    k_gemmT<<<(N + 127) / 128, 256, GSMEM>>>(nullptr, 2, N);               // 8
    k_agg<false><<<((long long)N * 32 + 255) / 256, 256>>>(b2, N);         // 9

    // pool + classifier
    k_pool<<<NGRAPH, HDIM>>>(batch, N);                                    // 10
    k_final<<<1, 640>>>(Wl, bl, out);                                      // 11
}

// round 9
// speedup vs baseline: 3.2057x; 1.1560x over previous
#include <cuda_runtime.h>
#include <cuda_bf16.h>
#include <cstdint>

// ---------------------------------------------------------------------------
// GCN forward, mma.sync bf16 HMMA GEMMs + bf16 intermediates.
// h1 = relu(conv(x,W1,b1)); h2 = conv(h1,W2,b2); pooled = segment_mean(h2);
// out = log_softmax(pooled@Wl + bl)
// conv(x,W,b) = dinv ⊙ (Adj_csr · (dinv ⊙ (x@W))) + b
// Dataflow: GEMM -> d_bufAh (bf16) -> agg1 -> d_bufBh (bf16) -> GEMM2
//           -> d_bufAh (bf16) -> agg2 -> d_bufB (fp32) -> pool.
// GEMM1 is my 4th launch (ncu capture slot).
// ---------------------------------------------------------------------------

#define MAXN 100000
#define MAXE 640000
#define MAXCSR (MAXN + MAXE)
#define NGRAPH 64
#define HDIM 128

__device__ __align__(16) __nv_bfloat16 d_bufAh[MAXN * HDIM];  // GEMM out / agg in
__device__ __align__(16) __nv_bfloat16 d_bufBh[MAXN * HDIM];  // agg1 out / GEMM2 in
__device__ __align__(16) float d_bufB[MAXN * HDIM];           // agg2 out (fp32, pooled)
__device__ __align__(16) float d_pool[NGRAPH * HDIM];
__device__ __align__(16) __nv_bfloat16 d_Wbf1[HDIM * HDIM];   // bf16 W1 [K][N]
__device__ __align__(16) __nv_bfloat16 d_Wbf2[HDIM * HDIM];   // bf16 W2 [K][N]
__device__ int   d_cnt[MAXN];
__device__ int   d_incl[MAXN];
__device__ int   d_bsum[128];
__device__ int   d_rowptr[MAXN + 1];
__device__ int   d_fill[MAXN];
__device__ int   d_csr[MAXCSR];
__device__ float d_dinv[MAXN];
__device__ int   d_is64;

__device__ __forceinline__ int loadIdx(const void* p, int i) {
    return d_is64 ? (int)((const long long*)p)[i] : ((const int*)p)[i];
}

__device__ __forceinline__ uint32_t smem_u32(const void* p) {
    uint32_t a;
    asm("{ .reg .u64 t; cvta.to.shared.u64 t, %1; cvt.u32.u64 %0, t; }" : "=r"(a) : "l"(p));
    return a;
}

// ---------------- setup: dtype detect + init cnt/fill ----------------------

__global__ void k_setup(const unsigned int* __restrict__ eiw, int N) {
    int i = blockIdx.x * blockDim.x + threadIdx.x;
    if (i < N) { d_cnt[i] = 1; d_fill[i] = 0; }          // cnt=1: self loop
    if (blockIdx.x == 0) {
        __shared__ unsigned long long ssum;
        if (threadIdx.x == 0) ssum = 0;
        __syncthreads();
        unsigned long long local = 0;
        for (int j = 1 + 2 * threadIdx.x; j < 4096; j += 2 * blockDim.x)
            local += eiw[j];
        atomicAdd(&ssum, local);
        __syncthreads();
        if (threadIdx.x == 0) d_is64 = (ssum == 0ULL) ? 1 : 0;
    }
}

// ---------------- degree count (+ W -> bf16 images, same [K][N] layout) ----

__global__ void k_count(const void* __restrict__ ei, int E,
                        const float* __restrict__ W1, const float* __restrict__ W2) {
    int e = blockIdx.x * blockDim.x + threadIdx.x;
    if (e < E) atomicAdd(&d_cnt[loadIdx(ei, E + e)], 1);   // dst row
    if (blockIdx.x < 64) {
        int idx = blockIdx.x * 256 + threadIdx.x;          // 0..16383
        d_Wbf1[idx] = __float2bfloat16(W1[idx]);
        d_Wbf2[idx] = __float2bfloat16(W2[idx]);
    }
}

// ---------------- block-level inclusive scan of degrees ----------------

__global__ void k_scan1(int N) {
    __shared__ int s[1024];
    int i = blockIdx.x * 1024 + threadIdx.x;
    int v = (i < N) ? d_cnt[i] : 0;
    if (i < N) d_dinv[i] = rsqrtf((float)v);
    s[threadIdx.x] = v;
    __syncthreads();
    for (int off = 1; off < 1024; off <<= 1) {
        int t = (threadIdx.x >= off) ? s[threadIdx.x - off] : 0;
        __syncthreads();
        s[threadIdx.x] += t;
        __syncthreads();
    }
    if (i < N) d_incl[i] = s[threadIdx.x];
    if (threadIdx.x == 1023) d_bsum[blockIdx.x] = s[1023];
}

__global__ void k_scan3b(int N, int nb) {
    int i = blockIdx.x * blockDim.x + threadIdx.x;
    if (i == 0) {
        int run = 0;
        for (int b = 0; b < nb; b++) run += d_bsum[b];
        d_rowptr[N] = run;
    }
    if (i < N) {
        int blk = i >> 10, base = 0;
        for (int b = 0; b < blk; b++) base += d_bsum[b];
        d_rowptr[i] = d_incl[i] - d_cnt[i] + base;
    }
}

__global__ void k_csrfill(const void* __restrict__ ei, int E, int N) {
    int id = blockIdx.x * blockDim.x + threadIdx.x;
    if (id >= E + N) return;
    int s, dn;
    if (id < E) { s = loadIdx(ei, id); dn = loadIdx(ei, E + id); }
    else        { s = dn = id - E; }                     // self loop
    int pos = d_rowptr[dn] + atomicAdd(&d_fill[dn], 1);
    d_csr[pos] = s;
}

// ---------------- HMMA GEMM: bufAh = dinv ⊙ (A @ W), 128x128 tile ----------
// 256 threads = 8 warps; warp tile 32x64 (2 x m16, 8 x n8), K in 8 steps of 16.
// srcSel 0: A = fp32 input x; else A = bf16 d_bufBh. Output bf16 d_bufAh.

#define SSTRIDE 136

__global__ void __launch_bounds__(256) k_gemmT(const float* __restrict__ Ain,
                                               int srcSel, int N) {
    const __nv_bfloat16* Wg = (srcSel == 0) ? d_Wbf1 : d_Wbf2;
    __nv_bfloat16* out = d_bufAh;

    extern __shared__ __align__(16) __nv_bfloat16 sm[];
    __nv_bfloat16* sA = sm;                    // [128][SSTRIDE]
    __nv_bfloat16* sB = sm + 128 * SSTRIDE;    // [128][SSTRIDE]

    int tid = threadIdx.x;
    int row0 = blockIdx.x * 128;

    if (srcSel == 0) {
        // A tile: fp32 -> bf16 (coalesced float4 = 4 cols), 4096 float4s
        for (int i = tid; i < 4096; i += 256) {
            int r = i >> 5, c4 = i & 31;
            float4 v = (row0 + r < N)
                ? ((const float4*)Ain)[(long long)(row0 + r) * 32 + c4]
                : make_float4(0.f, 0.f, 0.f, 0.f);
            __nv_bfloat162 p0 = __floats2bfloat162_rn(v.x, v.y);
            __nv_bfloat162 p1 = __floats2bfloat162_rn(v.z, v.w);
            *(__nv_bfloat162*)&sA[r * SSTRIDE + c4 * 4]     = p0;
            *(__nv_bfloat162*)&sA[r * SSTRIDE + c4 * 4 + 2] = p1;
        }
    } else {
        // A tile: bf16 rows, 16 uint4 per row
        for (int i = tid; i < 2048; i += 256) {
            int r = i >> 4, c8 = i & 15;
            uint4 v;
            if (row0 + r < N)
                v = ((const uint4*)d_bufBh)[(long long)(row0 + r) * 16 + c8];
            else
                v = make_uint4(0u, 0u, 0u, 0u);
            *(uint4*)&sA[r * SSTRIDE + c8 * 8] = v;
        }
    }
    // B tile: bf16 [128][128] -> smem stride 136, 16B chunks
    for (int i = tid; i < 2048; i += 256) {
        int r = i >> 4, c8 = i & 15;
        uint4 v = ((const uint4*)Wg)[i];
        *(uint4*)&sB[r * SSTRIDE + c8 * 8] = v;
    }
    __syncthreads();

    int warp = tid >> 5, lane = tid & 31;
    int wm = warp >> 1, wn = warp & 1;         // 4x2 warp grid
    int m_base = wm * 32, n_base = wn * 64;

    float acc[2][8][4];
#pragma unroll
    for (int mt = 0; mt < 2; mt++)
#pragma unroll
        for (int nt = 0; nt < 8; nt++)
#pragma unroll
            for (int q = 0; q < 4; q++) acc[mt][nt][q] = 0.f;

    uint32_t sAu = smem_u32(sA), sBu = smem_u32(sB);
    int lrow = lane & 15, lhalf = lane >> 4;   // ldmatrix address split

#pragma unroll
    for (int k0 = 0; k0 < 128; k0 += 16) {
        uint32_t a[2][4];
#pragma unroll
        for (int mt = 0; mt < 2; mt++) {
            uint32_t addr = sAu + (uint32_t)(((m_base + mt * 16 + lrow) * SSTRIDE
                                              + k0 + lhalf * 8) * 2);
            asm volatile("ldmatrix.sync.aligned.m8n8.x4.shared.b16 {%0,%1,%2,%3}, [%4];"
                         : "=r"(a[mt][0]), "=r"(a[mt][1]), "=r"(a[mt][2]), "=r"(a[mt][3])
                         : "r"(addr));
        }
        uint32_t b[4][4];
#pragma unroll
        for (int ng = 0; ng < 4; ng++) {
            uint32_t addr = sBu + (uint32_t)(((k0 + lrow) * SSTRIDE
                                              + n_base + ng * 16 + lhalf * 8) * 2);
            asm volatile("ldmatrix.sync.aligned.m8n8.x4.trans.shared.b16 {%0,%1,%2,%3}, [%4];"
                         : "=r"(b[ng][0]), "=r"(b[ng][1]), "=r"(b[ng][2]), "=r"(b[ng][3])
                         : "r"(addr));
        }
#pragma unroll
        for (int mt = 0; mt < 2; mt++)
#pragma unroll
            for (int nt = 0; nt < 8; nt++) {
                uint32_t b0 = b[nt >> 1][(nt & 1) * 2];
                uint32_t b1 = b[nt >> 1][(nt & 1) * 2 + 1];
                asm volatile(
                    "mma.sync.aligned.m16n8k16.row.col.f32.bf16.bf16.f32 "
                    "{%0,%1,%2,%3}, {%4,%5,%6,%7}, {%8,%9}, {%0,%1,%2,%3};"
                    : "+f"(acc[mt][nt][0]), "+f"(acc[mt][nt][1]),
                      "+f"(acc[mt][nt][2]), "+f"(acc[mt][nt][3])
                    : "r"(a[mt][0]), "r"(a[mt][1]), "r"(a[mt][2]), "r"(a[mt][3]),
                      "r"(b0), "r"(b1));
            }
    }

    // epilogue: bf16 out. frag rows lane>>2 and +8; cols (lane&3)*2 (+1)
    int rhi = lane >> 2, clo = (lane & 3) * 2;
#pragma unroll
    for (int mt = 0; mt < 2; mt++) {
        int rA = row0 + m_base + mt * 16 + rhi;
        int rB = rA + 8;
        float ddA = (rA < N) ? d_dinv[rA] : 0.f;
        float ddB = (rB < N) ? d_dinv[rB] : 0.f;
#pragma unroll
        for (int nt = 0; nt < 8; nt++) {
            int col = n_base + nt * 8 + clo;
            if (rA < N) {
                __nv_bfloat162 v = __floats2bfloat162_rn(acc[mt][nt][0] * ddA,
                                                         acc[mt][nt][1] * ddA);
                *(__nv_bfloat162*)&out[(long long)rA * 128 + col] = v;
            }
            if (rB < N) {
                __nv_bfloat162 v = __floats2bfloat162_rn(acc[mt][nt][2] * ddB,
                                                         acc[mt][nt][3] * ddB);
                *(__nv_bfloat162*)&out[(long long)rB * 128 + col] = v;
            }
        }
    }
}

// ---------------- Aggregation: warp per node, bf16 gather ------------------
// lane handles 4 cols (uint2 = 4 bf16 per row). OUT_BF16: write d_bufBh else d_bufB.

template <bool RELU, bool OUT_BF16>
__global__ void k_agg(const float* __restrict__ bias, int N) {
    int w    = (blockIdx.x * blockDim.x + threadIdx.x) >> 5;
    int lane = threadIdx.x & 31;
    if (w >= N) return;
    int rs = d_rowptr[w], re = d_rowptr[w + 1];
    const uint2* in2 = (const uint2*)d_bufAh;    // 32 uint2 chunks per row
    float4 acc = make_float4(0.f, 0.f, 0.f, 0.f);
    for (int e = rs; e < re; e++) {
        int s = d_csr[e];
        uint2 v = __ldg(&in2[(long long)s * 32 + lane]);
        __nv_bfloat162 p0 = *(__nv_bfloat162*)&v.x;
        __nv_bfloat162 p1 = *(__nv_bfloat162*)&v.y;
        float2 f0 = __bfloat1622float2(p0);
        float2 f1 = __bfloat1622float2(p1);
        acc.x += f0.x; acc.y += f0.y; acc.z += f1.x; acc.w += f1.y;
    }
    float dd = d_dinv[w];
    float4 b = __ldg(&((const float4*)bias)[lane]);
    float4 o = make_float4(acc.x * dd + b.x, acc.y * dd + b.y,
                           acc.z * dd + b.z, acc.w * dd + b.w);
    if (RELU) {
        o.x = fmaxf(o.x, 0.f); o.y = fmaxf(o.y, 0.f);
        o.z = fmaxf(o.z, 0.f); o.w = fmaxf(o.w, 0.f);
    }
    if (OUT_BF16) {
        __nv_bfloat162 q0 = __floats2bfloat162_rn(o.x, o.y);
        __nv_bfloat162 q1 = __floats2bfloat162_rn(o.z, o.w);
        uint2 pv; pv.x = *(uint32_t*)&q0; pv.y = *(uint32_t*)&q1;
        ((uint2*)d_bufBh)[(long long)w * 32 + lane] = pv;
    } else {
        ((float4*)d_bufB)[(long long)w * 32 + lane] = o;
    }
}

// ---------------- Mean pool per graph (batch sorted, branch-free) ----------

__global__ void k_pool(const void* __restrict__ batch, int N) {
    int g = blockIdx.x;        // 0..63
    int c = threadIdx.x;       // 0..127
    int lo = 0, hi = N;
    while (lo < hi) { int mid = (lo + hi) >> 1; if (loadIdx(batch, mid) < g) lo = mid + 1; else hi = mid; }
    int s = lo;
    lo = s; hi = N;
    while (lo < hi) { int mid = (lo + hi) >> 1; if (loadIdx(batch, mid) < g + 1) lo = mid + 1; else hi = mid; }
    int e = lo;
    float sum = 0.f;
    for (int i = s; i < e; i++) sum += d_bufB[(long long)i * 128 + c];
    float cnt = (float)((e - s) > 0 ? (e - s) : 1);
    d_pool[g * 128 + c] = sum / cnt;
}

// ---------------- Final: logits + log_softmax ----------------

__global__ void k_final(const float* __restrict__ Wl, const float* __restrict__ bl,
                        float* __restrict__ out) {
    __shared__ float sl[NGRAPH][10];
    __shared__ float sm[NGRAPH];
    __shared__ float ss[NGRAPH];
    int tid = threadIdx.x;                // 640 threads
    int g = tid / 10, c = tid % 10;
    if (tid < NGRAPH * 10) {
        float dot = bl[c];
        for (int k = 0; k < 128; k++) dot += d_pool[g * 128 + k] * Wl[k * 10 + c];
        sl[g][c] = dot;
    }
    __syncthreads();
    if (tid < NGRAPH) {
        float m = -1e30f;
        for (int j = 0; j < 10; j++) m = fmaxf(m, sl[tid][j]);
        float s = 0.f;
        for (int j = 0; j < 10; j++) s += expf(sl[tid][j] - m);
        sm[tid] = m; ss[tid] = logf(s);
    }
    __syncthreads();
    if (tid < NGRAPH * 10) out[tid] = sl[g][c] - sm[g] - ss[g];
}

// ---------------- Launch ----------------

extern "C" void kernel_launch(void* const* d_in, const int* in_sizes, int n_in,
                              void* d_out, int out_size) {
    (void)n_in; (void)out_size;
    const float* x     = (const float*)d_in[0];
    const void*  ei    = d_in[1];
    const void*  batch = d_in[2];
    const float* W1    = (const float*)d_in[3];
    const float* b1    = (const float*)d_in[4];
    const float* W2    = (const float*)d_in[5];
    const float* b2    = (const float*)d_in[6];
    const float* Wl    = (const float*)d_in[7];
    const float* bl    = (const float*)d_in[8];
    float* out = (float*)d_out;

    int N = in_sizes[0] / HDIM;
    int E = in_sizes[1] / 2;
    int nb = (N + 1023) >> 10;

    const int GSMEM = 2 * 128 * SSTRIDE * 2;   // 69632 bytes
    static int smemSet = 0;
    if (!smemSet) {
        cudaFuncSetAttribute(k_gemmT, cudaFuncAttributeMaxDynamicSharedMemorySize, GSMEM);
        smemSet = 1;
    }

    // ncu capture slot = my 4th launch -> GEMM1 there.
    k_setup <<<(N + 255) / 256, 256>>>((const unsigned int*)ei, N);        // 1
    k_count <<<(E + 255) / 256, 256>>>(ei, E, W1, W2);                     // 2 (+W bf16)
    k_scan1 <<<nb, 1024>>>(N);                                             // 3
    k_gemmT <<<(N + 127) / 128, 256, GSMEM>>>(x, 0, N);                    // 4 <- profiled
    k_scan3b<<<(N + 255) / 256, 256>>>(N, nb);                             // 5
    k_csrfill<<<(E + N + 255) / 256, 256>>>(ei, E, N);                     // 6
    k_agg<true, true><<<((long long)N * 32 + 255) / 256, 256>>>(b1, N);    // 7

    // conv2
    k_gemmT<<<(N + 127) / 128, 256, GSMEM>>>(nullptr, 2, N);               // 8
    k_agg<false, false><<<((long long)N * 32 + 255) / 256, 256>>>(b2, N);  // 9

    // pool + classifier
    k_pool<<<NGRAPH, HDIM>>>(batch, N);                                    // 10
    k_final<<<1, 640>>>(Wl, bl, out);                                      // 11
}